// round 14
// baseline (speedup 1.0000x reference)
#include <cuda_runtime.h>
#include <cuda_bf16.h>
#include <cstdint>

#define CUT 512
#define IMG_W 4096
#define HW (4096u * 4096u)
#define PLANE (512u * 512u)
#define IMG_STRIDE (3u * 512u * 512u)

// oy-major schedule (R13 win) + overview fast path:
// For z=0, x taps are exactly {8ox+3, 8ox+4} with wx=wy=0.5, and both live in
// the lane's own 16B-aligned float4 pair -> two LDG.128 per (row,channel)
// replace two 8-line scalar gathers (L1tex replays halved). Crops unchanged.
__global__ __launch_bounds__(256)
void dango_cutouts_kernel(const float* __restrict__ img,
                          const int* __restrict__ sizes,
                          const int* __restrict__ offy,
                          const int* __restrict__ offx,
                          float* __restrict__ out) {
    const int ox = blockIdx.x * 256 + threadIdx.x;  // 0..511
    const int z  = blockIdx.y;                      // 0 = overview, 1..12 = inner crops
    const int oy = blockIdx.z;                      // 0..511 (slowest: all z at same oy band)

    const unsigned pix = (unsigned)oy * (unsigned)CUT + (unsigned)ox;

    if (z == 0) {
        // ---- overview: exact taps y0=8oy+3, y1=8oy+4, x0=8ox+3, x1=8ox+4; w=0.5 ----
        const unsigned r0 = (unsigned)(8 * oy + 3) * (unsigned)IMG_W;
        const unsigned gx = (unsigned)(8 * ox);      // group base float idx (16B aligned)

        float rgb[3];
        #pragma unroll
        for (int c = 0; c < 3; c++) {
            const float4* __restrict__ p0 =
                (const float4*)(img + (unsigned)c * HW + r0 + gx);
            const float4* __restrict__ p1 =
                (const float4*)(img + (unsigned)c * HW + r0 + (unsigned)IMG_W + gx);
            float4 a0 = __ldg(p0);      // row y0, floats 8ox..8ox+3  (tap x0 = .w)
            float4 b0 = __ldg(p0 + 1);  // row y0, floats 8ox+4..+7   (tap x1 = .x)
            float4 a1 = __ldg(p1);      // row y1
            float4 b1 = __ldg(p1 + 1);
            // same arithmetic shape as reference with wx=wy=0.5
            float top = a0.w * 0.5f + b0.x * 0.5f;
            float bot = a1.w * 0.5f + b1.x * 0.5f;
            rgb[c] = top * 0.5f + bot * 0.5f;
        }
        const float gray = 0.2989f * rgb[0] + 0.587f * rgb[1] + 0.114f * rgb[2];

        // One sample feeds all 4 overview images; flipped(y,x)=full(y,511-x)
        const unsigned pixf = (unsigned)oy * (unsigned)CUT + (unsigned)(CUT - 1 - ox);
        #pragma unroll
        for (int c = 0; c < 3; c++) {
            __stcs(out + 0u * IMG_STRIDE + (unsigned)c * PLANE + pix,  rgb[c]);
            __stcs(out + 1u * IMG_STRIDE + (unsigned)c * PLANE + pix,  gray);
            __stcs(out + 2u * IMG_STRIDE + (unsigned)c * PLANE + pixf, rgb[c]);
            __stcs(out + 3u * IMG_STRIDE + (unsigned)c * PLANE + pixf, gray);
        }
        return;
    }

    // ---- inner crops (unchanged scalar gather path) ----
    const int size = sizes[z - 1];
    const int ioy  = offy[z - 1];
    const int iox  = offx[z - 1];

    const float s     = (float)size;
    const float offyf = (float)ioy;
    const float offxf = (float)iox;

    float y = offyf + (((float)oy + 0.5f) * s * (1.0f / 512.0f) - 0.5f);
    y = fminf(fmaxf(y, offyf), offyf + s - 1.0f);
    int   y0 = (int)floorf(y);
    float wy = y - (float)y0;
    int   dy = (y0 + 1 <= ioy + size - 1) ? 1 : 0;

    float x = offxf + (((float)ox + 0.5f) * s * (1.0f / 512.0f) - 0.5f);
    x = fminf(fmaxf(x, offxf), offxf + s - 1.0f);
    int   x0 = (int)floorf(x);
    float wx = x - (float)x0;
    int   dx = (x0 + 1 <= iox + size - 1) ? 1 : 0;

    const unsigned base = (unsigned)y0 * (unsigned)IMG_W + (unsigned)x0;
    const unsigned drow = (unsigned)dy * (unsigned)IMG_W;

    float v[3][4];
    #pragma unroll
    for (int c = 0; c < 3; c++) {
        const float* __restrict__ p = img + (unsigned)c * HW + base;
        v[c][0] = __ldg(p);
        v[c][1] = __ldg(p + dx);
        v[c][2] = __ldg(p + drow);
        v[c][3] = __ldg(p + drow + dx);
    }

    float rgb[3];
    #pragma unroll
    for (int c = 0; c < 3; c++) {
        float top = v[c][0] * (1.0f - wx) + v[c][1] * wx;
        float bot = v[c][2] * (1.0f - wx) + v[c][3] * wx;
        rgb[c] = top * (1.0f - wy) + bot * wy;
    }
    const float gray = 0.2989f * rgb[0] + 0.587f * rgb[1] + 0.114f * rgb[2];

    const unsigned base_o = (unsigned)(3 + z) * IMG_STRIDE;
    if (z == 1) {
        #pragma unroll
        for (int c = 0; c < 3; c++)
            __stcs(out + base_o + (unsigned)c * PLANE + pix, gray);
    } else {
        #pragma unroll
        for (int c = 0; c < 3; c++)
            __stcs(out + base_o + (unsigned)c * PLANE + pix, rgb[c]);
    }
}

extern "C" void kernel_launch(void* const* d_in, const int* in_sizes, int n_in,
                              void* d_out, int out_size) {
    const float* img   = (const float*)d_in[0];   // (1,3,4096,4096) fp32
    // d_in[1] = t (unused scalar)
    const int*   sizes = (const int*)d_in[2];     // (12,)
    const int*   offy  = (const int*)d_in[3];     // (12,)
    const int*   offx  = (const int*)d_in[4];     // (12,)
    float* out = (float*)d_out;                   // (16,3,512,512) fp32

    dim3 block(256, 1, 1);
    dim3 grid(CUT / 256, 13, CUT);  // oy slowest: all z-slices sweep rows together
    dango_cutouts_kernel<<<grid, block>>>(img, sizes, offy, offx, out);
}

// round 15
// speedup vs baseline: 1.0091x; 1.0091x over previous
#include <cuda_runtime.h>
#include <cuda_bf16.h>
#include <cstdint>

#define CUT 512
#define IMG_W 4096
#define HW (4096u * 4096u)
#define PLANE (512u * 512u)
#define IMG_STRIDE (3u * 512u * 512u)

// oy-major schedule (R13 win) with 128-thread blocks: same 100% theoretical
// occupancy (32 regs), but the concurrent-CTA set spans a ~2x tighter oy
// window -> cross-slice source-row overlap re-resolves in L2 sooner.
// Overview keeps the float4 fast path (fewer issued instructions).
__global__ __launch_bounds__(128)
void dango_cutouts_kernel(const float* __restrict__ img,
                          const int* __restrict__ sizes,
                          const int* __restrict__ offy,
                          const int* __restrict__ offx,
                          float* __restrict__ out) {
    const int ox = blockIdx.x * 128 + threadIdx.x;  // 0..511
    const int z  = blockIdx.y;                      // 0 = overview, 1..12 = inner crops
    const int oy = blockIdx.z;                      // 0..511 (slowest)

    const unsigned pix = (unsigned)oy * (unsigned)CUT + (unsigned)ox;

    if (z == 0) {
        // ---- overview: exact taps y0=8oy+3, y1=8oy+4, x0=8ox+3, x1=8ox+4; w=0.5 ----
        const unsigned r0 = (unsigned)(8 * oy + 3) * (unsigned)IMG_W;
        const unsigned gx = (unsigned)(8 * ox);      // 16B-aligned group base

        float rgb[3];
        #pragma unroll
        for (int c = 0; c < 3; c++) {
            const float4* __restrict__ p0 =
                (const float4*)(img + (unsigned)c * HW + r0 + gx);
            const float4* __restrict__ p1 =
                (const float4*)(img + (unsigned)c * HW + r0 + (unsigned)IMG_W + gx);
            float4 a0 = __ldg(p0);      // row y0: tap x0 = .w
            float4 b0 = __ldg(p0 + 1);  // row y0: tap x1 = .x
            float4 a1 = __ldg(p1);      // row y1
            float4 b1 = __ldg(p1 + 1);
            float top = a0.w * 0.5f + b0.x * 0.5f;
            float bot = a1.w * 0.5f + b1.x * 0.5f;
            rgb[c] = top * 0.5f + bot * 0.5f;
        }
        const float gray = 0.2989f * rgb[0] + 0.587f * rgb[1] + 0.114f * rgb[2];

        // One sample feeds all 4 overview images; flipped(y,x)=full(y,511-x)
        const unsigned pixf = (unsigned)oy * (unsigned)CUT + (unsigned)(CUT - 1 - ox);
        #pragma unroll
        for (int c = 0; c < 3; c++) {
            __stcs(out + 0u * IMG_STRIDE + (unsigned)c * PLANE + pix,  rgb[c]);
            __stcs(out + 1u * IMG_STRIDE + (unsigned)c * PLANE + pix,  gray);
            __stcs(out + 2u * IMG_STRIDE + (unsigned)c * PLANE + pixf, rgb[c]);
            __stcs(out + 3u * IMG_STRIDE + (unsigned)c * PLANE + pixf, gray);
        }
        return;
    }

    // ---- inner crops (scalar gather path) ----
    const int size = sizes[z - 1];
    const int ioy  = offy[z - 1];
    const int iox  = offx[z - 1];

    const float s     = (float)size;
    const float offyf = (float)ioy;
    const float offxf = (float)iox;

    float y = offyf + (((float)oy + 0.5f) * s * (1.0f / 512.0f) - 0.5f);
    y = fminf(fmaxf(y, offyf), offyf + s - 1.0f);
    int   y0 = (int)floorf(y);
    float wy = y - (float)y0;
    int   dy = (y0 + 1 <= ioy + size - 1) ? 1 : 0;

    float x = offxf + (((float)ox + 0.5f) * s * (1.0f / 512.0f) - 0.5f);
    x = fminf(fmaxf(x, offxf), offxf + s - 1.0f);
    int   x0 = (int)floorf(x);
    float wx = x - (float)x0;
    int   dx = (x0 + 1 <= iox + size - 1) ? 1 : 0;

    const unsigned base = (unsigned)y0 * (unsigned)IMG_W + (unsigned)x0;
    const unsigned drow = (unsigned)dy * (unsigned)IMG_W;

    float v[3][4];
    #pragma unroll
    for (int c = 0; c < 3; c++) {
        const float* __restrict__ p = img + (unsigned)c * HW + base;
        v[c][0] = __ldg(p);
        v[c][1] = __ldg(p + dx);
        v[c][2] = __ldg(p + drow);
        v[c][3] = __ldg(p + drow + dx);
    }

    float rgb[3];
    #pragma unroll
    for (int c = 0; c < 3; c++) {
        float top = v[c][0] * (1.0f - wx) + v[c][1] * wx;
        float bot = v[c][2] * (1.0f - wx) + v[c][3] * wx;
        rgb[c] = top * (1.0f - wy) + bot * wy;
    }
    const float gray = 0.2989f * rgb[0] + 0.587f * rgb[1] + 0.114f * rgb[2];

    const unsigned base_o = (unsigned)(3 + z) * IMG_STRIDE;
    if (z == 1) {
        #pragma unroll
        for (int c = 0; c < 3; c++)
            __stcs(out + base_o + (unsigned)c * PLANE + pix, gray);
    } else {
        #pragma unroll
        for (int c = 0; c < 3; c++)
            __stcs(out + base_o + (unsigned)c * PLANE + pix, rgb[c]);
    }
}

extern "C" void kernel_launch(void* const* d_in, const int* in_sizes, int n_in,
                              void* d_out, int out_size) {
    const float* img   = (const float*)d_in[0];   // (1,3,4096,4096) fp32
    // d_in[1] = t (unused scalar)
    const int*   sizes = (const int*)d_in[2];     // (12,)
    const int*   offy  = (const int*)d_in[3];     // (12,)
    const int*   offx  = (const int*)d_in[4];     // (12,)
    float* out = (float*)d_out;                   // (16,3,512,512) fp32

    dim3 block(128, 1, 1);
    dim3 grid(CUT / 128, 13, CUT);  // oy slowest; tighter in-flight oy window
    dango_cutouts_kernel<<<grid, block>>>(img, sizes, offy, offx, out);
}